// round 16
// baseline (speedup 1.0000x reference)
#include <cuda_runtime.h>
#include <cuda_bf16.h>
#include <math.h>

#define Bb 16
#define Nn 1000
#define NP 1024       // padded scan length (rows >= Nn forced to weight 0)
#define Hh 128
#define Mm 2
#define Tt 16
#define Ss 16         // chunks per (b,m): CN rows each (over padded NP)
#define CN 64         // NP / Ss; 8 warps x 8 rows
#define NEGC 1e8f
#define CCLIP 10.0f

// ---------------- scratch (static device globals; no allocation) ----------------
// r/v arrays padded by 32 rows so padded reads stay in-bounds (earlier slabs
// overrun into the next slab: valid memory, contribution masked to 0).
// __align__(32): glimpse uses 32-byte vector loads.
#define BNH (Bb*Nn*Hh)
#define PAD (32*Hh)
__device__ __align__(32) __nv_bfloat16 d_r1[Mm*BNH + PAD];
__device__ __align__(32) __nv_bfloat16 d_v1[Mm*BNH + PAD];
__device__ __align__(32) __nv_bfloat16 d_r3[Mm*BNH + PAD];
__device__ __align__(32) __nv_bfloat16 d_v3[Mm*BNH + PAD];
__device__ __align__(32) __nv_bfloat16 d_r4[Mm*BNH + PAD];
__device__ __align__(32) __nv_bfloat16 d_v4[Mm*BNH + PAD];
__device__ __align__(32) float d_r2[BNH + PAD];    // pointer path stays fp32
__device__ __align__(16) float d_hmean[Bb*Hh];
__device__ __align__(16) float d_qproj[Bb*Mm*Hh];  // projected glimpse query per head
__device__ __align__(16) float d_qp2[Bb*Hh];       // projected pointer query
__device__ __align__(16) float d_mask[Bb*Nn + 64];
__device__ __align__(16) float d_pZ[Bb*Mm*Ss];
__device__ __align__(16) float d_pacc[Bb*Mm*Ss*Hh];

__device__ __forceinline__ float fast_tanh(float x) {
    float y;
    asm("tanh.approx.f32 %0, %1;" : "=f"(y) : "f"(x));
    return y;
}

// 256-bit evict_last load (legal form on sm_100: .v4.b64)
__device__ __forceinline__ ulonglong4 ldg_el_256(const void* p) {
    ulonglong4 v;
    asm("ld.global.nc.L2::evict_last.v4.b64 {%0,%1,%2,%3},[%4];"
        : "=l"(v.x), "=l"(v.y), "=l"(v.z), "=l"(v.w) : "l"(p));
    return v;
}

// unpack one u64 (4 bf16) to 4 floats
__device__ __forceinline__ void bf16x4_to_f(unsigned long long u, float* o) {
    unsigned int lo = (unsigned int)u;
    unsigned int hi = (unsigned int)(u >> 32);
    float2 a = __bfloat1622float2(*(__nv_bfloat162*)&lo);
    float2 b = __bfloat1622float2(*(__nv_bfloat162*)&hi);
    o[0] = a.x; o[1] = a.y; o[2] = b.x; o[3] = b.y;
}

// ---------------- precompute GEMM: 13 slabs of [16000x128] @ [128x128] (SIMT) ------
struct GemmW {
    const float* Wref1; const float* Vec1;
    const float* Wref3; const float* Vec3;
    const float* Wref4; const float* Vec4;
    const float* Wref2;
};

__global__ __launch_bounds__(256) void gemm_kernel(const float* __restrict__ A, GemmW gw) {
    __shared__ float As[8][132];
    __shared__ float Bs[8][132];

    int s = blockIdx.y;
    int m = s & 1;
    const float* W;
    __nv_bfloat16* Db = nullptr;
    float* Df = nullptr;
    switch (s >> 1) {
        case 0: W = gw.Wref1; Db = d_r1; break;
        case 1: W = gw.Vec1;  Db = d_v1; break;
        case 2: W = gw.Wref3; Db = d_r3; break;
        case 3: W = gw.Vec3;  Db = d_v3; break;
        case 4: W = gw.Wref4; Db = d_r4; break;
        case 5: W = gw.Vec4;  Db = d_v4; break;
        default: W = gw.Wref2; Df = d_r2; break;   // s==12 -> m==0
    }
    W += (size_t)m * Hh * Hh;
    if (Db) Db += (size_t)m * BNH;

    int tid = threadIdx.x;
    int tx = tid & 15, ty = tid >> 4;
    int rowBase = blockIdx.x * 128;

    int arow = tid >> 1, akq = (tid & 1) * 4;
    int brow = tid >> 5, bcol = (tid & 31) * 4;

    float acc[8][8];
#pragma unroll
    for (int i = 0; i < 8; i++)
#pragma unroll
        for (int j = 0; j < 8; j++) acc[i][j] = 0.f;

    for (int k0 = 0; k0 < 128; k0 += 8) {
        float4 av = *(const float4*)&A[(size_t)(rowBase + arow) * 128 + k0 + akq];
        As[akq + 0][arow] = av.x;
        As[akq + 1][arow] = av.y;
        As[akq + 2][arow] = av.z;
        As[akq + 3][arow] = av.w;
        float4 bv = *(const float4*)&W[(size_t)(k0 + brow) * 128 + bcol];
        *(float4*)&Bs[brow][bcol] = bv;
        __syncthreads();
#pragma unroll
        for (int kk = 0; kk < 8; kk++) {
            float4 a0 = *(float4*)&As[kk][ty * 8];
            float4 a1 = *(float4*)&As[kk][ty * 8 + 4];
            float4 b0 = *(float4*)&Bs[kk][tx * 4];
            float4 b1 = *(float4*)&Bs[kk][64 + tx * 4];
            float a[8] = {a0.x, a0.y, a0.z, a0.w, a1.x, a1.y, a1.z, a1.w};
            float b[8] = {b0.x, b0.y, b0.z, b0.w, b1.x, b1.y, b1.z, b1.w};
#pragma unroll
            for (int i = 0; i < 8; i++)
#pragma unroll
                for (int j = 0; j < 8; j++) acc[i][j] = fmaf(a[i], b[j], acc[i][j]);
        }
        __syncthreads();
    }

    int r0 = rowBase + ty * 8;
    if (Db) {
#pragma unroll
        for (int i = 0; i < 8; i++) {
            __nv_bfloat162 p01 = __floats2bfloat162_rn(acc[i][0], acc[i][1]);
            __nv_bfloat162 p23 = __floats2bfloat162_rn(acc[i][2], acc[i][3]);
            __nv_bfloat162 p45 = __floats2bfloat162_rn(acc[i][4], acc[i][5]);
            __nv_bfloat162 p67 = __floats2bfloat162_rn(acc[i][6], acc[i][7]);
            uint2 lo, hi;
            lo.x = *(unsigned int*)&p01; lo.y = *(unsigned int*)&p23;
            hi.x = *(unsigned int*)&p45; hi.y = *(unsigned int*)&p67;
            *(uint2*)&Db[(size_t)(r0 + i) * Hh + tx * 4] = lo;
            *(uint2*)&Db[(size_t)(r0 + i) * Hh + 64 + tx * 4] = hi;
        }
    } else {
#pragma unroll
        for (int i = 0; i < 8; i++) {
            float4 o0 = make_float4(acc[i][0], acc[i][1], acc[i][2], acc[i][3]);
            float4 o1 = make_float4(acc[i][4], acc[i][5], acc[i][6], acc[i][7]);
            *(float4*)&Df[(size_t)(r0 + i) * Hh + tx * 4] = o0;
            *(float4*)&Df[(size_t)(r0 + i) * Hh + 64 + tx * 4] = o1;
        }
    }
}

// ---------------- h_mean ----------------
__global__ __launch_bounds__(256) void hmean_kernel(const float* __restrict__ enc) {
    int b = blockIdx.x;
    int h = threadIdx.x & 127;
    int part = threadIdx.x >> 7;
    float sum = 0.f;
    int n0 = part * 500;
    for (int n = n0; n < n0 + 500; n++) sum += enc[(size_t)(b * Nn + n) * Hh + h];
    __shared__ float sp[256];
    sp[threadIdx.x] = sum;
    __syncthreads();
    if (part == 0) d_hmean[b * Hh + h] = (sp[h] + sp[128 + h]) * (1.0f / (float)Nn);
}

// ---------------- init: mask copy + first-step Wq1 projection ----------------
__global__ __launch_bounds__(256) void init_kernel(const float* __restrict__ mask0,
                                                   const float* __restrict__ dec_inp,
                                                   const float* __restrict__ Wq1) {
    int b = blockIdx.x, tid = threadIdx.x;
    __shared__ float sq0[256];
    sq0[tid] = (tid < 128) ? d_hmean[b * Hh + tid] : dec_inp[tid - 128];
    for (int n = tid; n < Nn; n += 256) d_mask[b * Nn + n] = mask0[b * Nn + n];
    __syncthreads();
    int m = tid >> 7, h = tid & 127;
    const float* W = Wq1 + (size_t)m * 256 * Hh;
    float acc = 0.f;
#pragma unroll 8
    for (int i = 0; i < 256; i++) acc = fmaf(sq0[i], W[(size_t)i * Hh + h], acc);
    d_qproj[(b * Mm + m) * Hh + h] = acc;
}

// ---------------- glimpse chunk: 32B evict_last lanes, 8 lanes/row -----------------
// grid (Ss=16, Mm, Bb) = 512 blocks. 8 warps. Warp w owns rows [c*64+w*8, +8),
// processed as 2 iterations x 4 rows (row group g = lane>>3; lane owns 16 bf16
// = 32B at column p*16, p = lane&7). evict_last biases L2 to retain the 57MB
// decode working set across the revisit gap.
__global__ __launch_bounds__(256, 3) void glimpse_chunk(int which) {
    const __nv_bfloat16* rT = (which == 0) ? d_r1 : (which == 1) ? d_r3 : d_r4;
    const __nv_bfloat16* vT = (which == 0) ? d_v1 : (which == 1) ? d_v3 : d_v4;

    int c = blockIdx.x, m = blockIdx.y, b = blockIdx.z;
    int tid = threadIdx.x, lane = tid & 31, w = tid >> 5;
    int g = lane >> 3, p = lane & 7;

    __shared__ float wZ[8];
    __shared__ __align__(16) float wacc[8 * 128];

    // loop-invariant query slice: q[p*16 .. p*16+16)
    float qreg[16];
    {
        const float* qs = &d_qproj[((size_t)(b * Mm + m)) * Hh + p * 16];
#pragma unroll
        for (int j = 0; j < 16; j += 4) {
            float4 t = *(const float4*)&qs[j];
            qreg[j] = t.x; qreg[j + 1] = t.y; qreg[j + 2] = t.z; qreg[j + 3] = t.w;
        }
    }

    const __nv_bfloat16* rBase = rT + (size_t)(m * Bb + b) * Nn * Hh;
    const __nv_bfloat16* vBase = vT + (size_t)(m * Bb + b) * Nn * Hh;
    const float* maskb = d_mask + b * Nn;

    int nw = c * CN + w * 8;

    // front-batched 32B loads: 4 big LDGs in flight per lane
    ulonglong4 rw[2], vw[2];
    float mk[2];
#pragma unroll
    for (int i = 0; i < 2; i++) {
        int n = nw + i * 4 + g;
        rw[i] = ldg_el_256(&rBase[(size_t)n * Hh + p * 16]);
        vw[i] = ldg_el_256(&vBase[(size_t)n * Hh + p * 16]);
        mk[i] = maskb[n];
    }

    float Z = 0.f;
    float racc[16];
#pragma unroll
    for (int j = 0; j < 16; j++) racc[j] = 0.f;

#pragma unroll
    for (int i = 0; i < 2; i++) {
        // dot over this lane's 16 elements (stream-convert, temps die fast)
        float d = 0.f;
        const unsigned long long* ru = (const unsigned long long*)&rw[i];
        const unsigned long long* vu = (const unsigned long long*)&vw[i];
#pragma unroll
        for (int q = 0; q < 4; q++) {
            float rf[4], vf[4];
            bf16x4_to_f(ru[q], rf);
            bf16x4_to_f(vu[q], vf);
#pragma unroll
            for (int j = 0; j < 4; j++)
                d = fmaf(fast_tanh(qreg[q * 4 + j] + rf[j]), vf[j], d);
        }
        // reduce over the 8-lane row group
        d += __shfl_xor_sync(0xffffffffu, d, 1);
        d += __shfl_xor_sync(0xffffffffu, d, 2);
        d += __shfl_xor_sync(0xffffffffu, d, 4);

        float pw = __expf(fmaf(CCLIP, fast_tanh(d), -CCLIP) - NEGC * mk[i]);
        int n = nw + i * 4 + g;
        pw = (n < Nn) ? pw : 0.f;        // padding rows contribute nothing
        Z += pw;
        // weighted accumulate (reconvert r; rw stays live)
#pragma unroll
        for (int q = 0; q < 4; q++) {
            float rf[4];
            bf16x4_to_f(ru[q], rf);
#pragma unroll
            for (int j = 0; j < 4; j++)
                racc[q * 4 + j] = fmaf(pw, rf[j], racc[q * 4 + j]);
        }
    }

    // merge the 4 row groups (offsets 8,16 cross groups exactly)
#pragma unroll
    for (int off = 8; off <= 16; off <<= 1) {
        Z += __shfl_xor_sync(0xffffffffu, Z, off);
#pragma unroll
        for (int j = 0; j < 16; j++)
            racc[j] += __shfl_xor_sync(0xffffffffu, racc[j], off);
    }

    if (lane < 8) {
#pragma unroll
        for (int j = 0; j < 16; j += 4)
            *(float4*)&wacc[w * 128 + lane * 16 + j] =
                make_float4(racc[j], racc[j + 1], racc[j + 2], racc[j + 3]);
    }
    if (lane == 0) wZ[w] = Z;
    __syncthreads();

    if (tid < 128) {
        float z = 0.f, gsum = 0.f;
#pragma unroll
        for (int j = 0; j < 8; j++) {
            z += wZ[j];
            gsum += wacc[j * 128 + tid];
        }
        int pidx = (b * Mm + m) * Ss + c;
        d_pacc[pidx * Hh + tid] = gsum;
        if (tid == 0) d_pZ[pidx] = z;
    }
}

// ---------------- combine: 512 threads, 4-way-split matvecs ------------------------
// last==0: project with Wqnext[M,H,H] -> d_qproj. last==1: project with Wq2 -> d_qp2.
__global__ __launch_bounds__(512) void glimpse_combine(const float* __restrict__ Wmh,
                                                       const float* __restrict__ Wqnext,
                                                       int last,
                                                       const float* __restrict__ Wq2) {
    int b = blockIdx.x, tid = threadIdx.x;
    int q2 = tid >> 8;          // 0/1
    int mh = tid & 255;
    int m = mh >> 7, h = mh & 127;

    __shared__ float spz[512], spg[512];
    __shared__ float sg[256];
    __shared__ float sp[512];
    __shared__ __align__(16) float sqb[128];

    // chunk sums: 16 chunks split 8/8 across q2
    {
        int base = (b * Mm + m) * Ss;
        float z = 0.f, g = 0.f;
#pragma unroll
        for (int c = q2 * 8; c < q2 * 8 + 8; c++) {
            z += d_pZ[base + c];
            g += d_pacc[(base + c) * Hh + h];
        }
        spz[tid] = z; spg[tid] = g;
        __syncthreads();
        if (tid < 256) {
            float zz = spz[tid] + spz[tid + 256];
            float gg = spg[tid] + spg[tid + 256];
            sg[tid] = gg / zz;
        }
        __syncthreads();
    }
    // qb[h] = sum_{j<256} sg[j]*Wmh[j,h]; 4-way split
    {
        int pp = tid >> 7, hh = tid & 127;
        int j0 = pp * 64;
        float o = 0.f;
#pragma unroll 8
        for (int j = j0; j < j0 + 64; j++) o = fmaf(sg[j], Wmh[(size_t)j * Hh + hh], o);
        sp[tid] = o;
        __syncthreads();
        if (tid < 128) sqb[tid] = sp[tid] + sp[tid + 128] + sp[tid + 256] + sp[tid + 384];
        __syncthreads();
    }
    if (!last) {
        const float* W = Wqnext + (size_t)m * Hh * Hh;
        int i0 = q2 * 64;
        float acc = 0.f;
#pragma unroll 8
        for (int i = i0; i < i0 + 64; i++) acc = fmaf(sqb[i], W[(size_t)i * Hh + h], acc);
        sp[tid] = acc;
        __syncthreads();
        if (tid < 256) d_qproj[(b * Mm + m) * Hh + h] = sp[tid] + sp[tid + 256];
    } else {
        int pp = tid >> 7, hh = tid & 127;
        int i0 = pp * 32;
        float acc = 0.f;
#pragma unroll 8
        for (int i = i0; i < i0 + 32; i++) acc = fmaf(sqb[i], Wq2[(size_t)i * Hh + hh], acc);
        sp[tid] = acc;
        __syncthreads();
        if (tid < 128) d_qp2[b * Hh + tid] = sp[tid] + sp[tid + 128] + sp[tid + 256] + sp[tid + 384];
    }
}

// ---------------- fused pointer: logits + log_softmax + argmax + state -------------
__global__ __launch_bounds__(1024) void pointer_kernel(const float* __restrict__ enc,
                                                       const float* __restrict__ Wq1,
                                                       const float* __restrict__ Vec2,
                                                       float* __restrict__ out, int t) {
    int b = blockIdx.x, tid = threadIdx.x, lane = tid & 31, w = tid >> 5;
    __shared__ float su[Nn];
    __shared__ float rv[1024];
    __shared__ int ri[1024];
    __shared__ float sred[1024];
    __shared__ float sq0[256];

    // ---- logits ----
    {
        float4 q4 = *(const float4*)&d_qp2[b * Hh + lane * 4];
        float4 v2 = *(const float4*)&Vec2[lane * 4];
        const float* rBase = d_r2 + (size_t)b * Nn * Hh;
        const float* maskb = d_mask + b * Nn;
#pragma unroll
        for (int j = 0; j < 8; j++) {
            float4 r[4]; float mk[4];
#pragma unroll
            for (int k = 0; k < 4; k++) {
                int n = w + (j * 4 + k) * 32;
                if (n < Nn) {
                    r[k] = *(const float4*)&rBase[(size_t)n * Hh + lane * 4];
                    mk[k] = maskb[n];
                } else {
                    r[k] = make_float4(0.f, 0.f, 0.f, 0.f);
                    mk[k] = 0.f;
                }
            }
            float dot[4];
#pragma unroll
            for (int k = 0; k < 4; k++) {
                float d = fast_tanh(q4.x + r[k].x) * v2.x;
                d = fmaf(fast_tanh(q4.y + r[k].y), v2.y, d);
                d = fmaf(fast_tanh(q4.z + r[k].z), v2.z, d);
                d = fmaf(fast_tanh(q4.w + r[k].w), v2.w, d);
                dot[k] = d;
            }
#pragma unroll
            for (int off = 16; off; off >>= 1) {
#pragma unroll
                for (int k = 0; k < 4; k++) dot[k] += __shfl_xor_sync(0xffffffffu, dot[k], off);
            }
            if (lane == 0) {
#pragma unroll
                for (int k = 0; k < 4; k++) {
                    int n = w + (j * 4 + k) * 32;
                    if (n < Nn)
                        su[n] = CCLIP * fast_tanh(dot[k]) - NEGC * maskb[n];
                }
            }
        }
    }
    __syncthreads();

    float u = (tid < Nn) ? su[tid] : -1e30f;

    // argmax (first index wins on ties, matching jnp.argmax)
    rv[tid] = u; ri[tid] = (tid < Nn) ? tid : 0;
    __syncthreads();
#pragma unroll
    for (int s = 512; s; s >>= 1) {
        if (tid < s) {
            float v2r = rv[tid + s]; int i2 = ri[tid + s];
            if (v2r > rv[tid] || (v2r == rv[tid] && i2 < ri[tid])) { rv[tid] = v2r; ri[tid] = i2; }
        }
        __syncthreads();
    }
    int sel = ri[0];

    // fixed-shift lse: u <= 10 always
    sred[tid] = (tid < Nn) ? __expf(u - CCLIP) : 0.f;
    __syncthreads();
#pragma unroll
    for (int s = 512; s; s >>= 1) {
        if (tid < s) sred[tid] += sred[tid + s];
        __syncthreads();
    }
    float lse = CCLIP + __logf(sred[0]);

    if (tid < Nn)
        out[((size_t)t * Bb + b) * Nn + tid] = u - lse;
    if (tid == 0) {
        out[(size_t)Tt * Bb * Nn + t * Bb + b] = (float)sel;
        d_mask[b * Nn + sel] = 1.0f;
    }

    // q0 = [h_mean, enc[b, sel]]; project with Wq1 for next step's glimpse 1
    if (tid < 256)
        sq0[tid] = (tid < 128) ? d_hmean[b * Hh + tid]
                               : enc[((size_t)b * Nn + sel) * Hh + (tid - 128)];
    __syncthreads();
    {
        int part = tid >> 8;          // 4 parts
        int mh = tid & 255;
        int m = mh >> 7, h = mh & 127;
        const float* W = Wq1 + (size_t)m * 256 * Hh;
        int i0 = part * 64;
        float acc = 0.f;
#pragma unroll 8
        for (int i = i0; i < i0 + 64; i++) acc = fmaf(sq0[i], W[(size_t)i * Hh + h], acc);
        sred[tid] = acc;
        __syncthreads();
        if (tid < 256) {
            float a = sred[tid] + sred[tid + 256] + sred[tid + 512] + sred[tid + 768];
            d_qproj[(b * Mm + m) * Hh + h] = a;
        }
    }
}

// ---------------- host launcher ----------------
extern "C" void kernel_launch(void* const* d_in, const int* in_sizes, int n_in,
                              void* d_out, int out_size) {
    const float* enc    = (const float*)d_in[0];
    const float* mask0  = (const float*)d_in[1];
    const float* Wq1    = (const float*)d_in[2];
    const float* Wref1  = (const float*)d_in[3];
    const float* Vec1   = (const float*)d_in[4];
    const float* Wq3    = (const float*)d_in[5];
    const float* Wref3  = (const float*)d_in[6];
    const float* Vec3   = (const float*)d_in[7];
    const float* Wq4    = (const float*)d_in[8];
    const float* Wref4  = (const float*)d_in[9];
    const float* Vec4   = (const float*)d_in[10];
    const float* Wmh    = (const float*)d_in[11];
    const float* Wq2    = (const float*)d_in[12];
    const float* Wref2  = (const float*)d_in[13];
    const float* Vec2   = (const float*)d_in[14];
    const float* dec_inp = (const float*)d_in[15];
    float* out = (float*)d_out;

    GemmW gw{Wref1, Vec1, Wref3, Vec3, Wref4, Vec4, Wref2};
    gemm_kernel<<<dim3(125, 13), 256>>>(enc, gw);
    hmean_kernel<<<Bb, 256>>>(enc);
    init_kernel<<<Bb, 256>>>(mask0, dec_inp, Wq1);

    for (int t = 0; t < Tt; t++) {
        glimpse_chunk<<<dim3(Ss, Mm, Bb), 256>>>(0);
        glimpse_combine<<<Bb, 512>>>(Wmh, Wq3, 0, Wq2);
        glimpse_chunk<<<dim3(Ss, Mm, Bb), 256>>>(1);
        glimpse_combine<<<Bb, 512>>>(Wmh, Wq4, 0, Wq2);
        glimpse_chunk<<<dim3(Ss, Mm, Bb), 256>>>(2);
        glimpse_combine<<<Bb, 512>>>(Wmh, Wq4, 1, Wq2);
        pointer_kernel<<<Bb, 1024>>>(enc, Wq1, Vec2, out, t);
    }
    (void)in_sizes; (void)n_in; (void)out_size;
}